// round 2
// baseline (speedup 1.0000x reference)
#include <cuda_runtime.h>

#define DM 2048
#define HD 128
#define FF 512
#define MT 64          // tokens per CTA
#define FC 128         // FF chunk
#define NTHREADS 256
#define XS_STRIDE 132  // padded row stride for Xs [MT][HD]
#define HS_STRIDE 132  // padded row stride for Hs [MT][FC]
#define WS_N 128       // weight slice [16][128]

typedef unsigned long long u64;

__device__ __forceinline__ u64 pack_dup(float v) {
    u64 r; asm("mov.b64 %0, {%1, %2};" : "=l"(r) : "f"(v), "f"(v)); return r;
}
__device__ __forceinline__ u64 pack2(float lo, float hi) {
    u64 r; asm("mov.b64 %0, {%1, %2};" : "=l"(r) : "f"(lo), "f"(hi)); return r;
}
__device__ __forceinline__ void unpack2(u64 v, float& lo, float& hi) {
    asm("mov.b64 {%0, %1}, %2;" : "=f"(lo), "=f"(hi) : "l"(v));
}
__device__ __forceinline__ u64 ffma2(u64 a, u64 b, u64 c) {
    u64 d; asm("fma.rn.f32x2 %0, %1, %2, %3;" : "=l"(d) : "l"(a), "l"(b), "l"(c)); return d;
}

// one 4Mx8N micro-tile k-step: A scalars (dup-packed), B as 4 natural f32x2 pairs
__device__ __forceinline__ void micro_fma(u64 (&acc)[4][4],
                                          float a0, float a1, float a2, float a3,
                                          const float* wrow, int tx) {
    ulonglong2 w0 = *reinterpret_cast<const ulonglong2*>(wrow + tx * 8);
    ulonglong2 w1 = *reinterpret_cast<const ulonglong2*>(wrow + tx * 8 + 4);
    u64 am[4] = { pack_dup(a0), pack_dup(a1), pack_dup(a2), pack_dup(a3) };
    u64 bp[4] = { w0.x, w0.y, w1.x, w1.y };
    #pragma unroll
    for (int i = 0; i < 4; ++i)
        #pragma unroll
        for (int j = 0; j < 4; ++j)
            acc[i][j] = ffma2(am[i], bp[j], acc[i][j]);
}

__global__ void __launch_bounds__(NTHREADS, 2) mhffn_kernel(
    const float* __restrict__ x,  const float* __restrict__ W1,
    const float* __restrict__ b1, const float* __restrict__ W2,
    const float* __restrict__ b2, float* __restrict__ out)
{
    extern __shared__ float smem[];
    float* Xs = smem;                                   // [MT][XS_STRIDE]
    float* Hs = smem + MT * XS_STRIDE;                  // [MT][HS_STRIDE]
    float* Ws = smem + MT * (XS_STRIDE + HS_STRIDE);    // [16][WS_N]

    const int h   = blockIdx.y;
    const int m0  = blockIdx.x * MT;
    const int tid = threadIdx.x;
    const int tx  = tid & 15;   // N direction (8 cols each)
    const int ty  = tid >> 4;   // M direction (4 rows each)

    // ---- load X tile [MT x HD] (natural layout, coalesced float4) ----
    #pragma unroll
    for (int it = 0; it < 8; ++it) {
        int lin = it * NTHREADS + tid;      // 64 rows x 32 float4
        int m  = lin >> 5;
        int k4 = (lin & 31) << 2;
        float4 v = *reinterpret_cast<const float4*>(
            x + (size_t)(m0 + m) * DM + h * HD + k4);
        *reinterpret_cast<float4*>(&Xs[m * XS_STRIDE + k4]) = v;
    }

    // ---- persistent output accumulators, init with b2 ----
    u64 oacc[4][4];
    {
        const float* bp = b2 + h * HD + tx * 8;
        float4 bA = *reinterpret_cast<const float4*>(bp);
        float4 bB = *reinterpret_cast<const float4*>(bp + 4);
        u64 p0 = pack2(bA.x, bA.y), p1 = pack2(bA.z, bA.w);
        u64 p2 = pack2(bB.x, bB.y), p3 = pack2(bB.z, bB.w);
        #pragma unroll
        for (int i = 0; i < 4; ++i) {
            oacc[i][0] = p0; oacc[i][1] = p1; oacc[i][2] = p2; oacc[i][3] = p3;
        }
    }

    // weight-slice loader thread mapping: 512 float4 per 16x128 slice, 2 per thread
    const int pk0 = tid >> 5,           pc0 = (tid & 31) << 2;        // rows 0..7
    const int pk1 = (tid + 256) >> 5,   pc1 = pc0;                    // rows 8..15

    #pragma unroll 1
    for (int fc = 0; fc < FF; fc += FC) {
        // ============ stage 1: H = relu(X @ W1[:, fc:fc+FC] + b1) ============
        u64 acc[4][4];
        #pragma unroll
        for (int i = 0; i < 4; ++i)
            #pragma unroll
            for (int j = 0; j < 4; ++j) acc[i][j] = 0ull;

        const float* w1b = W1 + ((size_t)h * HD) * FF + fc;
        float4 pre0 = *reinterpret_cast<const float4*>(w1b + (size_t)pk0 * FF + pc0);
        float4 pre1 = *reinterpret_cast<const float4*>(w1b + (size_t)pk1 * FF + pc1);

        #pragma unroll 1
        for (int s = 0; s < 8; ++s) {
            __syncthreads();   // previous slice consumers done (also covers Xs/Hs init)
            *reinterpret_cast<float4*>(&Ws[pk0 * WS_N + pc0]) = pre0;
            *reinterpret_cast<float4*>(&Ws[pk1 * WS_N + pc1]) = pre1;
            if (s < 7) {
                pre0 = *reinterpret_cast<const float4*>(
                    w1b + (size_t)((s + 1) * 16 + pk0) * FF + pc0);
                pre1 = *reinterpret_cast<const float4*>(
                    w1b + (size_t)((s + 1) * 16 + pk1) * FF + pc1);
            }
            __syncthreads();   // slice visible
            #pragma unroll
            for (int kk = 0; kk < 16; ++kk) {
                int k = s * 16 + kk;
                float a0 = Xs[(ty * 4 + 0) * XS_STRIDE + k];
                float a1 = Xs[(ty * 4 + 1) * XS_STRIDE + k];
                float a2 = Xs[(ty * 4 + 2) * XS_STRIDE + k];
                float a3 = Xs[(ty * 4 + 3) * XS_STRIDE + k];
                micro_fma(acc, a0, a1, a2, a3, &Ws[kk * WS_N], tx);
            }
        }

        // epilogue: bias + relu -> Hs[m][f_local]  (8B packed stores)
        {
            const float* b1p = b1 + (size_t)h * FF + fc + tx * 8;
            float4 bt0 = *reinterpret_cast<const float4*>(b1p);
            float4 bt1 = *reinterpret_cast<const float4*>(b1p + 4);
            float bv[8] = { bt0.x, bt0.y, bt0.z, bt0.w, bt1.x, bt1.y, bt1.z, bt1.w };
            #pragma unroll
            for (int i = 0; i < 4; ++i)
                #pragma unroll
                for (int j2 = 0; j2 < 4; ++j2) {
                    float lo, hi;
                    unpack2(acc[i][j2], lo, hi);
                    lo = fmaxf(lo + bv[2 * j2],     0.0f);
                    hi = fmaxf(hi + bv[2 * j2 + 1], 0.0f);
                    *reinterpret_cast<u64*>(
                        &Hs[(ty * 4 + i) * HS_STRIDE + tx * 8 + j2 * 2]) = pack2(lo, hi);
                }
        }

        // ============ stage 2: out += relu(H) @ W2[fc:fc+FC, :] ============
        const float* w2b = W2 + ((size_t)h * FF + fc) * HD;
        pre0 = *reinterpret_cast<const float4*>(w2b + (size_t)pk0 * HD + pc0);
        pre1 = *reinterpret_cast<const float4*>(w2b + (size_t)pk1 * HD + pc1);

        #pragma unroll 1
        for (int s = 0; s < 8; ++s) {
            __syncthreads();   // prev consumers done; also orders Hs writes before reads
            *reinterpret_cast<float4*>(&Ws[pk0 * WS_N + pc0]) = pre0;
            *reinterpret_cast<float4*>(&Ws[pk1 * WS_N + pc1]) = pre1;
            if (s < 7) {
                pre0 = *reinterpret_cast<const float4*>(
                    w2b + (size_t)((s + 1) * 16 + pk0) * HD + pc0);
                pre1 = *reinterpret_cast<const float4*>(
                    w2b + (size_t)((s + 1) * 16 + pk1) * HD + pc1);
            }
            __syncthreads();
            #pragma unroll
            for (int kk = 0; kk < 16; ++kk) {
                int f = s * 16 + kk;
                float a0 = Hs[(ty * 4 + 0) * HS_STRIDE + f];
                float a1 = Hs[(ty * 4 + 1) * HS_STRIDE + f];
                float a2 = Hs[(ty * 4 + 2) * HS_STRIDE + f];
                float a3 = Hs[(ty * 4 + 3) * HS_STRIDE + f];
                micro_fma(oacc, a0, a1, a2, a3, &Ws[kk * WS_N], tx);
            }
        }
    }

    // ---- write output tile ----
    #pragma unroll
    for (int i = 0; i < 4; ++i) {
        float o0, o1, o2, o3, o4, o5, o6, o7;
        unpack2(oacc[i][0], o0, o1);
        unpack2(oacc[i][1], o2, o3);
        unpack2(oacc[i][2], o4, o5);
        unpack2(oacc[i][3], o6, o7);
        size_t base = (size_t)(m0 + ty * 4 + i) * DM + h * HD + tx * 8;
        float4 v0 = make_float4(o0, o1, o2, o3);
        float4 v1 = make_float4(o4, o5, o6, o7);
        *reinterpret_cast<float4*>(out + base)     = v0;
        *reinterpret_cast<float4*>(out + base + 4) = v1;
    }
}

extern "C" void kernel_launch(void* const* d_in, const int* in_sizes, int n_in,
                              void* d_out, int out_size) {
    const float* x  = (const float*)d_in[0];
    const float* W1 = (const float*)d_in[1];
    const float* b1 = (const float*)d_in[2];
    const float* W2 = (const float*)d_in[3];
    const float* b2 = (const float*)d_in[4];
    float* out = (float*)d_out;

    int M = in_sizes[0] / DM;   // total tokens (16384)
    size_t smem = (size_t)(MT * (XS_STRIDE + HS_STRIDE) + 16 * WS_N) * sizeof(float);
    cudaFuncSetAttribute(mhffn_kernel, cudaFuncAttributeMaxDynamicSharedMemorySize,
                         (int)smem);
    dim3 grid(M / MT, 16);
    mhffn_kernel<<<grid, NTHREADS, smem>>>(x, W1, b1, W2, b2, out);
}

// round 8
// speedup vs baseline: 3.6481x; 3.6481x over previous
#include <cuda_runtime.h>
#include <cuda_bf16.h>
#include <stdint.h>

#define DM 2048
#define HD 128
#define FF 512
#define MT 128      // tokens per CTA
#define FC 128      // ff chunk
#define NT 512      // threads per CTA (16 warps, 4x4 warp grid)

// ---------------- bf16 hi/lo weight scratch (device globals, allowed) ----------
__device__ __nv_bfloat16 g_B1h[16 * FF * HD];   // [h][n=ff][k=hd]  = W1[h][k][n]
__device__ __nv_bfloat16 g_B1l[16 * FF * HD];
__device__ __nv_bfloat16 g_B2h[16 * HD * FF];   // [h][n=hd][k=ff]  = W2[h][k][n]
__device__ __nv_bfloat16 g_B2l[16 * HD * FF];

// ---------------- weight prep: fp32 -> transposed bf16 hi/lo -------------------
__global__ void prep_kernel(const float* __restrict__ W1, const float* __restrict__ W2) {
    int idx = blockIdx.x * blockDim.x + threadIdx.x;
    const int N1 = 16 * FF * HD;   // 1,048,576
    float v;
    if (idx < N1) {
        int k = idx & (HD - 1);
        int n = (idx >> 7) & (FF - 1);
        int h = idx >> 16;
        v = W1[((size_t)h * HD + k) * FF + n];
        __nv_bfloat16 hi = __float2bfloat16_rn(v);
        __nv_bfloat16 lo = __float2bfloat16_rn(v - __bfloat162float(hi));
        g_B1h[idx] = hi; g_B1l[idx] = lo;
    } else {
        int j = idx - N1;
        int k = j & (FF - 1);
        int n = (j >> 9) & (HD - 1);
        int h = j >> 16;
        v = W2[((size_t)h * FF + k) * HD + n];
        __nv_bfloat16 hi = __float2bfloat16_rn(v);
        __nv_bfloat16 lo = __float2bfloat16_rn(v - __bfloat162float(hi));
        g_B2h[j] = hi; g_B2l[j] = lo;
    }
}

// ---------------- helpers ------------------------------------------------------
__device__ __forceinline__ uint32_t smem_u32(const void* p) {
    uint32_t a;
    asm("{ .reg .u64 t; cvta.to.shared.u64 t, %1; cvt.u32.u64 %0, t; }" : "=r"(a) : "l"(p));
    return a;
}
__device__ __forceinline__ void ldsm4(uint32_t (&r)[4], uint32_t addr) {
    asm volatile("ldmatrix.sync.aligned.m8n8.x4.shared.b16 {%0,%1,%2,%3}, [%4];"
                 : "=r"(r[0]), "=r"(r[1]), "=r"(r[2]), "=r"(r[3]) : "r"(addr));
}
__device__ __forceinline__ void mma_bf16(float (&d)[4], const uint32_t (&a)[4],
                                         uint32_t b0, uint32_t b1) {
    asm volatile("mma.sync.aligned.m16n8k16.row.col.f32.bf16.bf16.f32 "
                 "{%0,%1,%2,%3}, {%4,%5,%6,%7}, {%8,%9}, {%0,%1,%2,%3};"
                 : "+f"(d[0]), "+f"(d[1]), "+f"(d[2]), "+f"(d[3])
                 : "r"(a[0]), "r"(a[1]), "r"(a[2]), "r"(a[3]), "r"(b0), "r"(b1));
}
__device__ __forceinline__ uint32_t pack_bf2(__nv_bfloat16 lo, __nv_bfloat16 hi) {
    return ((uint32_t)__bfloat16_as_ushort(hi) << 16) | __bfloat16_as_ushort(lo);
}

// Tile layout: [128 rows][128 bf16] = 32 KB, row stride 256B, 16B chunks XOR-swizzled
// by (row & 7): ldmatrix 8-row sets hit 8 distinct chunk positions -> conflict-free.
__device__ __forceinline__ uint32_t swz(int row, int chunk) {
    return (uint32_t)(row * 256 + ((chunk ^ (row & 7)) << 4));
}

// ---------------- SMEM layout (bytes) ------------------------------------------
#define SM_XH 0u
#define SM_XL 32768u
#define SM_HH 65536u
#define SM_HL 98304u
#define SM_WH 131072u
#define SM_WL 163840u
#define SM_B1S 196608u    // 128 floats
#define SM_B2S 197120u    // 128 floats
#define SMEM_BYTES 197632u

// one GEMM tile: acc[mt][nt] += Ah*Bh + Ah*Bl + Al*Bh, A/B 128x128 bf16 (k-major)
__device__ __forceinline__ void gemm_tile(uint32_t base, uint32_t aH, uint32_t aL,
                                          int lane, int wm, int wn,
                                          float (&acc)[2][4][4]) {
    const int arow0 = wm * 32 + (lane & 15);
    const int arow1 = arow0 + 16;
    const int ahalf = lane >> 4;                              // chunk offset 0/1
    const int brow0 = wn * 32 + (lane & 7) + ((lane >> 4) << 3);
    const int brow1 = brow0 + 16;
    const int bhalf = (lane >> 3) & 1;

    #pragma unroll
    for (int ks = 0; ks < 8; ++ks) {
        const int ca = ks * 2 + ahalf;
        const int cb = ks * 2 + bhalf;
        uint32_t ah0[4], ah1[4], al0[4], al1[4];
        uint32_t bh0[4], bh1[4], bl0[4], bl1[4];
        ldsm4(ah0, base + aH + swz(arow0, ca));
        ldsm4(ah1, base + aH + swz(arow1, ca));
        ldsm4(al0, base + aL + swz(arow0, ca));
        ldsm4(al1, base + aL + swz(arow1, ca));
        ldsm4(bh0, base + SM_WH + swz(brow0, cb));
        ldsm4(bh1, base + SM_WH + swz(brow1, cb));
        ldsm4(bl0, base + SM_WL + swz(brow0, cb));
        ldsm4(bl1, base + SM_WL + swz(brow1, cb));

        // Ah * Bh
        mma_bf16(acc[0][0], ah0, bh0[0], bh0[1]);
        mma_bf16(acc[0][1], ah0, bh0[2], bh0[3]);
        mma_bf16(acc[0][2], ah0, bh1[0], bh1[1]);
        mma_bf16(acc[0][3], ah0, bh1[2], bh1[3]);
        mma_bf16(acc[1][0], ah1, bh0[0], bh0[1]);
        mma_bf16(acc[1][1], ah1, bh0[2], bh0[3]);
        mma_bf16(acc[1][2], ah1, bh1[0], bh1[1]);
        mma_bf16(acc[1][3], ah1, bh1[2], bh1[3]);
        // Ah * Bl
        mma_bf16(acc[0][0], ah0, bl0[0], bl0[1]);
        mma_bf16(acc[0][1], ah0, bl0[2], bl0[3]);
        mma_bf16(acc[0][2], ah0, bl1[0], bl1[1]);
        mma_bf16(acc[0][3], ah0, bl1[2], bl1[3]);
        mma_bf16(acc[1][0], ah1, bl0[0], bl0[1]);
        mma_bf16(acc[1][1], ah1, bl0[2], bl0[3]);
        mma_bf16(acc[1][2], ah1, bl1[0], bl1[1]);
        mma_bf16(acc[1][3], ah1, bl1[2], bl1[3]);
        // Al * Bh
        mma_bf16(acc[0][0], al0, bh0[0], bh0[1]);
        mma_bf16(acc[0][1], al0, bh0[2], bh0[3]);
        mma_bf16(acc[0][2], al0, bh1[0], bh1[1]);
        mma_bf16(acc[0][3], al0, bh1[2], bh1[3]);
        mma_bf16(acc[1][0], al1, bh0[0], bh0[1]);
        mma_bf16(acc[1][1], al1, bh0[2], bh0[3]);
        mma_bf16(acc[1][2], al1, bh1[0], bh1[1]);
        mma_bf16(acc[1][3], al1, bh1[2], bh1[3]);
    }
}

__global__ void __launch_bounds__(NT, 1) mhffn_hmma(
    const float* __restrict__ x,  const float* __restrict__ b1,
    const float* __restrict__ b2, float* __restrict__ out)
{
    extern __shared__ char smem[];
    const uint32_t sb = smem_u32(smem);
    const int t    = threadIdx.x;
    const int lane = t & 31;
    const int wid  = t >> 5;
    const int wm   = wid >> 2;   // 0..3 (M direction, 32 rows each)
    const int wn   = wid & 3;    // 0..3 (N direction, 32 cols each)
    const int h    = blockIdx.y;
    const int m0   = blockIdx.x * MT;

    float* b1s = (float*)(smem + SM_B1S);
    float* b2s = (float*)(smem + SM_B2S);
    if (t < 128) b2s[t] = b2[h * HD + t];

    // ---- X tile load + bf16 hi/lo split ----
    #pragma unroll
    for (int i = 0; i < 8; ++i) {
        int lin = i * NT + t;               // 128 rows x 32 float4
        int row = lin >> 5;
        int k4  = (lin & 31) << 2;          // float index, multiple of 4
        float4 v = *(const float4*)(x + (size_t)(m0 + row) * DM + h * HD + k4);
        float vv[4] = { v.x, v.y, v.z, v.w };
        __nv_bfloat16 hh[4], ll[4];
        #pragma unroll
        for (int q = 0; q < 4; ++q) {
            hh[q] = __float2bfloat16_rn(vv[q]);
            ll[q] = __float2bfloat16_rn(vv[q] - __bfloat162float(hh[q]));
        }
        uint32_t o = swz(row, k4 >> 3) + ((k4 & 4) << 1);   // 8B-aligned within chunk
        *(uint2*)(smem + SM_XH + o) = make_uint2(pack_bf2(hh[0], hh[1]), pack_bf2(hh[2], hh[3]));
        *(uint2*)(smem + SM_XL + o) = make_uint2(pack_bf2(ll[0], ll[1]), pack_bf2(ll[2], ll[3]));
    }

    float oacc[2][4][4];
    #pragma unroll
    for (int i = 0; i < 2; ++i)
        #pragma unroll
        for (int j = 0; j < 4; ++j)
            #pragma unroll
            for (int q = 0; q < 4; ++q) oacc[i][j][q] = 0.0f;

    #pragma unroll 1
    for (int c = 0; c < 4; ++c) {
        __syncthreads();   // W buffer free (previous stage-2 LDSM complete); X visible
        if (t < 128) b1s[t] = b1[(size_t)h * FF + c * FC + t];
        // ---- copy W1 chunk [128 n][128 k] hi/lo into swizzled tiles ----
        {
            const __nv_bfloat16* p1h = g_B1h + ((size_t)h * FF + c * FC) * HD;
            const __nv_bfloat16* p1l = g_B1l + ((size_t)h * FF + c * FC) * HD;
            #pragma unroll
            for (int u = 0; u < 4; ++u) {
                int lin = u * NT + t;       // 128 rows x 16 chunks
                int row = lin >> 4;
                int cc  = lin & 15;
                uint32_t o = swz(row, cc);
                *(uint4*)(smem + SM_WH + o) = *(const uint4*)(p1h + (size_t)row * HD + cc * 8);
                *(uint4*)(smem + SM_WL + o) = *(const uint4*)(p1l + (size_t)row * HD + cc * 8);
            }
        }
        __syncthreads();

        // ---- stage 1: H = relu(X @ W1c + b1c) ----
        float acc[2][4][4];
        #pragma unroll
        for (int i = 0; i < 2; ++i)
            #pragma unroll
            for (int j = 0; j < 4; ++j)
                #pragma unroll
                for (int q = 0; q < 4; ++q) acc[i][j][q] = 0.0f;
        gemm_tile(sb, SM_XH, SM_XL, lane, wm, wn, acc);
        __syncthreads();   // all W1 LDSM done before W overwrite

        // H epilogue: +b1, relu, hi/lo split -> H tiles (A-layout [m][f])
        #pragma unroll
        for (int mt = 0; mt < 2; ++mt)
            #pragma unroll
            for (int nt = 0; nt < 4; ++nt) {
                int m = wm * 32 + mt * 16 + (lane >> 2);
                int f = wn * 32 + nt * 8 + 2 * (lane & 3);
                float v0 = fmaxf(acc[mt][nt][0] + b1s[f],     0.0f);
                float v1 = fmaxf(acc[mt][nt][1] + b1s[f + 1], 0.0f);
                float v2 = fmaxf(acc[mt][nt][2] + b1s[f],     0.0f);
                float v3 = fmaxf(acc[mt][nt][3] + b1s[f + 1], 0.0f);
                __nv_bfloat16 h0 = __float2bfloat16_rn(v0), h1 = __float2bfloat16_rn(v1);
                __nv_bfloat16 h2 = __float2bfloat16_rn(v2), h3 = __float2bfloat16_rn(v3);
                __nv_bfloat16 l0 = __float2bfloat16_rn(v0 - __bfloat162float(h0));
                __nv_bfloat16 l1 = __float2bfloat16_rn(v1 - __bfloat162float(h1));
                __nv_bfloat16 l2 = __float2bfloat16_rn(v2 - __bfloat162float(h2));
                __nv_bfloat16 l3 = __float2bfloat16_rn(v3 - __bfloat162float(h3));
                uint32_t o0 = swz(m,     f >> 3) + ((f & 7) << 1);
                uint32_t o1 = swz(m + 8, f >> 3) + ((f & 7) << 1);
                *(uint32_t*)(smem + SM_HH + o0) = pack_bf2(h0, h1);
                *(uint32_t*)(smem + SM_HL + o0) = pack_bf2(l0, l1);
                *(uint32_t*)(smem + SM_HH + o1) = pack_bf2(h2, h3);
                *(uint32_t*)(smem + SM_HL + o1) = pack_bf2(l2, l3);
            }

        // ---- copy W2 chunk [128 n][k slice 128] hi/lo ----
        {
            const __nv_bfloat16* p2h = g_B2h + (size_t)h * HD * FF + c * FC;
            const __nv_bfloat16* p2l = g_B2l + (size_t)h * HD * FF + c * FC;
            #pragma unroll
            for (int u = 0; u < 4; ++u) {
                int lin = u * NT + t;
                int row = lin >> 4;
                int cc  = lin & 15;
                uint32_t o = swz(row, cc);
                *(uint4*)(smem + SM_WH + o) = *(const uint4*)(p2h + (size_t)row * FF + cc * 8);
                *(uint4*)(smem + SM_WL + o) = *(const uint4*)(p2l + (size_t)row * FF + cc * 8);
            }
        }
        __syncthreads();   // W2 + H visible to all warps

        // ---- stage 2: OUT += H @ W2c ----
        gemm_tile(sb, SM_HH, SM_HL, lane, wm, wn, oacc);
    }

    // ---- OUT epilogue: +b2, write fp32 ----
    #pragma unroll
    for (int mt = 0; mt < 2; ++mt)
        #pragma unroll
        for (int nt = 0; nt < 4; ++nt) {
            int m = wm * 32 + mt * 16 + (lane >> 2);
            int n = wn * 32 + nt * 8 + 2 * (lane & 3);
            float2 v0 = make_float2(oacc[mt][nt][0] + b2s[n],
                                    oacc[mt][nt][1] + b2s[n + 1]);
            float2 v1 = make_float2(oacc[mt][nt][2] + b2s[n],
                                    oacc[mt][nt][3] + b2s[n + 1]);
            *(float2*)(out + (size_t)(m0 + m)     * DM + h * HD + n) = v0;
            *(float2*)(out + (size_t)(m0 + m + 8) * DM + h * HD + n) = v1;
        }
}

extern "C" void kernel_launch(void* const* d_in, const int* in_sizes, int n_in,
                              void* d_out, int out_size) {
    const float* x  = (const float*)d_in[0];
    const float* W1 = (const float*)d_in[1];
    const float* b1 = (const float*)d_in[2];
    const float* W2 = (const float*)d_in[3];
    const float* b2 = (const float*)d_in[4];
    float* out = (float*)d_out;

    // weight transpose + bf16 hi/lo split (every launch; deterministic)
    prep_kernel<<<8192, 256>>>(W1, W2);

    int M = in_sizes[0] / DM;   // 16384 tokens
    cudaFuncSetAttribute(mhffn_hmma, cudaFuncAttributeMaxDynamicSharedMemorySize,
                         (int)SMEM_BYTES);
    dim3 grid(M / MT, 16);
    mhffn_hmma<<<grid, NT, SMEM_BYTES>>>(x, b1, b2, out);
}

// round 11
// speedup vs baseline: 5.4821x; 1.5027x over previous
#include <cuda_runtime.h>
#include <cuda_fp16.h>
#include <stdint.h>

#define DM 2048
#define HD 128
#define FF 512
#define MT 128      // tokens per CTA
#define FC 128      // ff chunk
#define NT 512      // threads per CTA (16 warps, 4x4 warp grid)

// ---------------- fp16 transposed weight scratch (device globals) --------------
__device__ __half g_W1[16 * FF * HD];   // [h][n=ff][k=hd]  = W1[h][k][n]
__device__ __half g_W2[16 * HD * FF];   // [h][n=hd][k=ff]  = W2[h][k][n]

// ---------------- weight prep: fp32 -> transposed fp16 -------------------------
__global__ void prep_kernel(const float* __restrict__ W1, const float* __restrict__ W2) {
    int idx = blockIdx.x * blockDim.x + threadIdx.x;
    const int N1 = 16 * FF * HD;   // 1,048,576
    if (idx < N1) {
        int k = idx & (HD - 1);
        int n = (idx >> 7) & (FF - 1);
        int h = idx >> 16;
        g_W1[idx] = __float2half_rn(W1[((size_t)h * HD + k) * FF + n]);
    } else {
        int j = idx - N1;
        int k = j & (FF - 1);
        int n = (j >> 9) & (HD - 1);
        int h = j >> 16;
        g_W2[j] = __float2half_rn(W2[((size_t)h * FF + k) * HD + n]);
    }
}

// ---------------- helpers ------------------------------------------------------
__device__ __forceinline__ uint32_t smem_u32(const void* p) {
    uint32_t a;
    asm("{ .reg .u64 t; cvta.to.shared.u64 t, %1; cvt.u32.u64 %0, t; }" : "=r"(a) : "l"(p));
    return a;
}
__device__ __forceinline__ void ldsm4(uint32_t (&r)[4], uint32_t addr) {
    asm volatile("ldmatrix.sync.aligned.m8n8.x4.shared.b16 {%0,%1,%2,%3}, [%4];"
                 : "=r"(r[0]), "=r"(r[1]), "=r"(r[2]), "=r"(r[3]) : "r"(addr));
}
__device__ __forceinline__ void mma_f16(float (&d)[4], const uint32_t (&a)[4],
                                        uint32_t b0, uint32_t b1) {
    asm volatile("mma.sync.aligned.m16n8k16.row.col.f32.f16.f16.f32 "
                 "{%0,%1,%2,%3}, {%4,%5,%6,%7}, {%8,%9}, {%0,%1,%2,%3};"
                 : "+f"(d[0]), "+f"(d[1]), "+f"(d[2]), "+f"(d[3])
                 : "r"(a[0]), "r"(a[1]), "r"(a[2]), "r"(a[3]), "r"(b0), "r"(b1));
}
__device__ __forceinline__ uint32_t pack_h2(__half lo, __half hi) {
    return ((uint32_t)__half_as_ushort(hi) << 16) | __half_as_ushort(lo);
}
__device__ __forceinline__ void cp16(uint32_t dst, const void* src) {
    asm volatile("cp.async.cg.shared.global [%0], [%1], 16;" :: "r"(dst), "l"(src));
}
#define CP_COMMIT() asm volatile("cp.async.commit_group;" ::: "memory")
#define CP_WAIT(n)  asm volatile("cp.async.wait_group %0;" :: "n"(n) : "memory")

// Tile layout: [128 rows][128 f16] = 32 KB, row stride 256B, 16B chunks XOR-swizzled
// by (row & 7): ldmatrix 8-row sets hit 8 distinct chunk positions -> conflict-free.
__device__ __forceinline__ uint32_t swz(int row, int chunk) {
    return (uint32_t)(row * 256 + ((chunk ^ (row & 7)) << 4));
}

// ---------------- SMEM layout (bytes) ------------------------------------------
#define SM_XH  0u
#define SM_XL  32768u
#define SM_HH  65536u
#define SM_HL  98304u
#define SM_WA  131072u    // W double buffer A
#define SM_WB  163840u    // W double buffer B
#define SM_B1S 196608u    // 128 floats
#define SM_B2S 197120u    // 128 floats
#define SMEM_BYTES 197632u

// acc[mt][nt] += Ah @ B + Al @ B   (A,B 128x128 f16, k-major; 2-pass A-split)
__device__ __forceinline__ void gemm_tile(uint32_t base, uint32_t aH, uint32_t aL,
                                          uint32_t wOff, int lane, int wm, int wn,
                                          float (&acc)[2][4][4]) {
    const int arow0 = wm * 32 + (lane & 15);
    const int arow1 = arow0 + 16;
    const int ahalf = lane >> 4;                              // chunk offset 0/1
    const int brow0 = wn * 32 + (lane & 7) + ((lane >> 4) << 3);
    const int brow1 = brow0 + 16;
    const int bhalf = (lane >> 3) & 1;

    #pragma unroll
    for (int ks = 0; ks < 8; ++ks) {
        const int ca = ks * 2 + ahalf;
        const int cb = ks * 2 + bhalf;
        uint32_t ah0[4], ah1[4], al0[4], al1[4], b0[4], b1[4];
        ldsm4(ah0, base + aH + swz(arow0, ca));
        ldsm4(ah1, base + aH + swz(arow1, ca));
        ldsm4(al0, base + aL + swz(arow0, ca));
        ldsm4(al1, base + aL + swz(arow1, ca));
        ldsm4(b0,  base + wOff + swz(brow0, cb));
        ldsm4(b1,  base + wOff + swz(brow1, cb));

        // Ah * B
        mma_f16(acc[0][0], ah0, b0[0], b0[1]);
        mma_f16(acc[0][1], ah0, b0[2], b0[3]);
        mma_f16(acc[0][2], ah0, b1[0], b1[1]);
        mma_f16(acc[0][3], ah0, b1[2], b1[3]);
        mma_f16(acc[1][0], ah1, b0[0], b0[1]);
        mma_f16(acc[1][1], ah1, b0[2], b0[3]);
        mma_f16(acc[1][2], ah1, b1[0], b1[1]);
        mma_f16(acc[1][3], ah1, b1[2], b1[3]);
        // Al * B
        mma_f16(acc[0][0], al0, b0[0], b0[1]);
        mma_f16(acc[0][1], al0, b0[2], b0[3]);
        mma_f16(acc[0][2], al0, b1[0], b1[1]);
        mma_f16(acc[0][3], al0, b1[2], b1[3]);
        mma_f16(acc[1][0], al1, b0[0], b0[1]);
        mma_f16(acc[1][1], al1, b0[2], b0[3]);
        mma_f16(acc[1][2], al1, b1[0], b1[1]);
        mma_f16(acc[1][3], al1, b1[2], b1[3]);
    }
}

// async-copy one W chunk [128 rows][128 f16] into swizzled tile at wOff
__device__ __forceinline__ void w_copy_async(uint32_t base, uint32_t wOff,
                                             const __half* src, int rstride, int t) {
    #pragma unroll
    for (int u = 0; u < 4; ++u) {
        int lin = u * NT + t;       // 128 rows x 16 chunks of 16B
        int row = lin >> 4;
        int cc  = lin & 15;
        cp16(base + wOff + swz(row, cc), src + (size_t)row * rstride + cc * 8);
    }
}

__global__ void __launch_bounds__(NT, 1) mhffn_hmma(
    const float* __restrict__ x,  const float* __restrict__ b1,
    const float* __restrict__ b2, float* __restrict__ out)
{
    extern __shared__ char smem[];
    const uint32_t sb = smem_u32(smem);
    const int t    = threadIdx.x;
    const int lane = t & 31;
    const int wid  = t >> 5;
    const int wm   = wid >> 2;   // 0..3 (M direction, 32 rows each)
    const int wn   = wid & 3;    // 0..3 (N direction, 32 cols each)
    const int h    = blockIdx.y;
    const int m0   = blockIdx.x * MT;

    float* b1s = (float*)(smem + SM_B1S);
    float* b2s = (float*)(smem + SM_B2S);
    if (t < 128) b2s[t] = b2[h * HD + t];

    const __half* w1base = g_W1 + (size_t)h * FF * HD;   // [FF][HD]
    const __half* w2base = g_W2 + (size_t)h * HD * FF;   // [HD][FF]

    // ---- prefetch W1 chunk 0 into WA ----
    w_copy_async(sb, SM_WA, w1base, HD, t);
    CP_COMMIT();

    // ---- X tile load + fp16 hi/lo split ----
    #pragma unroll
    for (int i = 0; i < 8; ++i) {
        int lin = i * NT + t;               // 128 rows x 32 float4
        int row = lin >> 5;
        int k4  = (lin & 31) << 2;
        float4 v = *(const float4*)(x + (size_t)(m0 + row) * DM + h * HD + k4);
        float vv[4] = { v.x, v.y, v.z, v.w };
        __half hh[4], ll[4];
        #pragma unroll
        for (int q = 0; q < 4; ++q) {
            hh[q] = __float2half_rn(vv[q]);
            ll[q] = __float2half_rn(vv[q] - __half2float(hh[q]));
        }
        uint32_t o = swz(row, k4 >> 3) + ((k4 & 4) << 1);
        *(uint2*)(smem + SM_XH + o) = make_uint2(pack_h2(hh[0], hh[1]), pack_h2(hh[2], hh[3]));
        *(uint2*)(smem + SM_XL + o) = make_uint2(pack_h2(ll[0], ll[1]), pack_h2(ll[2], ll[3]));
    }

    float oacc[2][4][4];
    #pragma unroll
    for (int i = 0; i < 2; ++i)
        #pragma unroll
        for (int j = 0; j < 4; ++j)
            #pragma unroll
            for (int q = 0; q < 4; ++q) oacc[i][j][q] = 0.0f;

    #pragma unroll 1
    for (int c = 0; c < 4; ++c) {
        // ---- W1(c) arrived; X (c=0) / H-reads of prev chunk complete ----
        CP_WAIT(0);
        __syncthreads();
        if (t < 128) b1s[t] = b1[(size_t)h * FF + c * FC + t];

        // stream W2(c) into WB while gemm1 runs on WA
        w_copy_async(sb, SM_WB, w2base + c * FC, FF, t);
        CP_COMMIT();

        // ---- stage 1: H = relu(X @ W1c + b1c) ----
        float acc[2][4][4];
        #pragma unroll
        for (int i = 0; i < 2; ++i)
            #pragma unroll
            for (int j = 0; j < 4; ++j)
                #pragma unroll
                for (int q = 0; q < 4; ++q) acc[i][j][q] = 0.0f;
        gemm_tile(sb, SM_XH, SM_XL, SM_WA, lane, wm, wn, acc);
        __syncthreads();   // WA reads done (safe to refill); prev H reads long done

        // stream W1(c+1) into WA while epilogue runs (always commit: group math)
        if (c < 3) w_copy_async(sb, SM_WA, w1base + (size_t)(c + 1) * FC * HD, HD, t);
        CP_COMMIT();

        // H epilogue: +b1, relu, fp16 hi/lo split -> H tiles (A-layout [m][f])
        #pragma unroll
        for (int mt = 0; mt < 2; ++mt)
            #pragma unroll
            for (int nt = 0; nt < 4; ++nt) {
                int m = wm * 32 + mt * 16 + (lane >> 2);
                int f = wn * 32 + nt * 8 + 2 * (lane & 3);
                float v0 = fmaxf(acc[mt][nt][0] + b1s[f],     0.0f);
                float v1 = fmaxf(acc[mt][nt][1] + b1s[f + 1], 0.0f);
                float v2 = fmaxf(acc[mt][nt][2] + b1s[f],     0.0f);
                float v3 = fmaxf(acc[mt][nt][3] + b1s[f + 1], 0.0f);
                __half h0 = __float2half_rn(v0), h1 = __float2half_rn(v1);
                __half h2 = __float2half_rn(v2), h3 = __float2half_rn(v3);
                __half l0 = __float2half_rn(v0 - __half2float(h0));
                __half l1 = __float2half_rn(v1 - __half2float(h1));
                __half l2 = __float2half_rn(v2 - __half2float(h2));
                __half l3 = __float2half_rn(v3 - __half2float(h3));
                uint32_t o0 = swz(m,     f >> 3) + ((f & 7) << 1);
                uint32_t o1 = swz(m + 8, f >> 3) + ((f & 7) << 1);
                *(uint32_t*)(smem + SM_HH + o0) = pack_h2(h0, h1);
                *(uint32_t*)(smem + SM_HL + o0) = pack_h2(l0, l1);
                *(uint32_t*)(smem + SM_HH + o1) = pack_h2(h2, h3);
                *(uint32_t*)(smem + SM_HL + o1) = pack_h2(l2, l3);
            }

        // ---- W2(c) arrived (W1(c+1) may still be in flight); H visible ----
        CP_WAIT(1);
        __syncthreads();

        // ---- stage 2: OUT += H @ W2c ----
        gemm_tile(sb, SM_HH, SM_HL, SM_WB, lane, wm, wn, oacc);
    }

    // ---- OUT epilogue: +b2, write fp32 ----
    #pragma unroll
    for (int mt = 0; mt < 2; ++mt)
        #pragma unroll
        for (int nt = 0; nt < 4; ++nt) {
            int m = wm * 32 + mt * 16 + (lane >> 2);
            int n = wn * 32 + nt * 8 + 2 * (lane & 3);
            float2 v0 = make_float2(oacc[mt][nt][0] + b2s[n],
                                    oacc[mt][nt][1] + b2s[n + 1]);
            float2 v1 = make_float2(oacc[mt][nt][2] + b2s[n],
                                    oacc[mt][nt][3] + b2s[n + 1]);
            *(float2*)(out + (size_t)(m0 + m)     * DM + h * HD + n) = v0;
            *(float2*)(out + (size_t)(m0 + m + 8) * DM + h * HD + n) = v1;
        }
}

extern "C" void kernel_launch(void* const* d_in, const int* in_sizes, int n_in,
                              void* d_out, int out_size) {
    const float* x  = (const float*)d_in[0];
    const float* W1 = (const float*)d_in[1];
    const float* b1 = (const float*)d_in[2];
    const float* W2 = (const float*)d_in[3];
    const float* b2 = (const float*)d_in[4];
    float* out = (float*)d_out;

    // weight transpose + fp16 convert (every launch; deterministic)
    prep_kernel<<<8192, 256>>>(W1, W2);

    int M = in_sizes[0] / DM;   // 16384 tokens
    cudaFuncSetAttribute(mhffn_hmma, cudaFuncAttributeMaxDynamicSharedMemorySize,
                         (int)SMEM_BYTES);
    dim3 grid(M / MT, 16);
    mhffn_hmma<<<grid, NT, SMEM_BYTES>>>(x, b1, b2, out);
}

// round 14
// speedup vs baseline: 9.5414x; 1.7405x over previous
#include <cuda_runtime.h>
#include <cuda_fp16.h>
#include <stdint.h>

#define DM 2048
#define HD 128
#define FF 512
#define MT 64       // tokens per CTA
#define FC 128      // ff chunk
#define NT 256      // threads per CTA (8 warps, 2x4 warp grid)

// ---------------- fp16 transposed weight scratch (device globals) --------------
__device__ __half g_W1[16 * FF * HD];   // [h][n=ff][k=hd]  = W1[h][k][n]
__device__ __half g_W2[16 * HD * FF];   // [h][n=hd][k=ff]  = W2[h][k][n]

// ---------------- weight prep: fp32 -> transposed fp16 -------------------------
__global__ void prep_kernel(const float* __restrict__ W1, const float* __restrict__ W2) {
    int idx = blockIdx.x * blockDim.x + threadIdx.x;
    const int N1 = 16 * FF * HD;   // 1,048,576
    if (idx < N1) {
        int k = idx & (HD - 1);
        int n = (idx >> 7) & (FF - 1);
        int h = idx >> 16;
        g_W1[idx] = __float2half_rn(W1[((size_t)h * HD + k) * FF + n]);
    } else {
        int j = idx - N1;
        int k = j & (FF - 1);
        int n = (j >> 9) & (HD - 1);
        int h = j >> 16;
        g_W2[j] = __float2half_rn(W2[((size_t)h * FF + k) * HD + n]);
    }
}

// ---------------- helpers ------------------------------------------------------
__device__ __forceinline__ uint32_t smem_u32(const void* p) {
    uint32_t a;
    asm("{ .reg .u64 t; cvta.to.shared.u64 t, %1; cvt.u32.u64 %0, t; }" : "=r"(a) : "l"(p));
    return a;
}
__device__ __forceinline__ void ldsm4(uint32_t (&r)[4], uint32_t addr) {
    asm volatile("ldmatrix.sync.aligned.m8n8.x4.shared.b16 {%0,%1,%2,%3}, [%4];"
                 : "=r"(r[0]), "=r"(r[1]), "=r"(r[2]), "=r"(r[3]) : "r"(addr));
}
__device__ __forceinline__ void mma_f16(float (&d)[4], const uint32_t (&a)[4],
                                        uint32_t b0, uint32_t b1) {
    asm volatile("mma.sync.aligned.m16n8k16.row.col.f32.f16.f16.f32 "
                 "{%0,%1,%2,%3}, {%4,%5,%6,%7}, {%8,%9}, {%0,%1,%2,%3};"
                 : "+f"(d[0]), "+f"(d[1]), "+f"(d[2]), "+f"(d[3])
                 : "r"(a[0]), "r"(a[1]), "r"(a[2]), "r"(a[3]), "r"(b0), "r"(b1));
}
__device__ __forceinline__ uint32_t pack_h2(__half lo, __half hi) {
    return ((uint32_t)__half_as_ushort(hi) << 16) | __half_as_ushort(lo);
}
__device__ __forceinline__ void cp16(uint32_t dst, const void* src) {
    asm volatile("cp.async.cg.shared.global [%0], [%1], 16;" :: "r"(dst), "l"(src));
}
#define CP_COMMIT() asm volatile("cp.async.commit_group;" ::: "memory")
#define CP_WAIT(n)  asm volatile("cp.async.wait_group %0;" :: "n"(n) : "memory")

// Tile layout: [rows][128 f16], row stride 256B, 16B chunks XOR-swizzled
// by (row & 7): ldmatrix 8-row sets hit 8 distinct chunk positions -> conflict-free.
__device__ __forceinline__ uint32_t swz(int row, int chunk) {
    return (uint32_t)(row * 256 + ((chunk ^ (row & 7)) << 4));
}

// ---------------- SMEM layout (bytes) ------------------------------------------
#define SM_X   0u         // X tile   [64][128] f16 = 16 KB
#define SM_H   16384u     // H tile   [64][128] f16 = 16 KB
#define SM_WA  32768u     // W buf A  [128][128] f16 = 32 KB
#define SM_WB  65536u     // W buf B  [128][128] f16 = 32 KB
#define SM_B1S 98304u     // 128 floats
#define SM_B2S 98816u     // 128 floats
#define SMEM_BYTES 99328u

// acc[mt][nt] += A @ B   (A 64x128 f16 at aOff, B 128x128 f16 at wOff, k-major)
__device__ __forceinline__ void gemm_tile(uint32_t base, uint32_t aOff, uint32_t wOff,
                                          int lane, int wm, int wn,
                                          float (&acc)[2][4][4]) {
    const int arow0 = wm * 32 + (lane & 15);
    const int arow1 = arow0 + 16;
    const int ahalf = lane >> 4;                              // chunk offset 0/1
    const int brow0 = wn * 32 + (lane & 7) + ((lane >> 4) << 3);
    const int brow1 = brow0 + 16;
    const int bhalf = (lane >> 3) & 1;

    #pragma unroll
    for (int ks = 0; ks < 8; ++ks) {
        const int ca = ks * 2 + ahalf;
        const int cb = ks * 2 + bhalf;
        uint32_t a0[4], a1[4], b0[4], b1[4];
        ldsm4(a0, base + aOff + swz(arow0, ca));
        ldsm4(a1, base + aOff + swz(arow1, ca));
        ldsm4(b0, base + wOff + swz(brow0, cb));
        ldsm4(b1, base + wOff + swz(brow1, cb));

        mma_f16(acc[0][0], a0, b0[0], b0[1]);
        mma_f16(acc[0][1], a0, b0[2], b0[3]);
        mma_f16(acc[0][2], a0, b1[0], b1[1]);
        mma_f16(acc[0][3], a0, b1[2], b1[3]);
        mma_f16(acc[1][0], a1, b0[0], b0[1]);
        mma_f16(acc[1][1], a1, b0[2], b0[3]);
        mma_f16(acc[1][2], a1, b1[0], b1[1]);
        mma_f16(acc[1][3], a1, b1[2], b1[3]);
    }
}

// async-copy one W chunk [128 rows][128 f16] into swizzled tile at wOff
__device__ __forceinline__ void w_copy_async(uint32_t base, uint32_t wOff,
                                             const __half* src, int rstride, int t) {
    #pragma unroll
    for (int u = 0; u < 8; ++u) {
        int lin = u * NT + t;       // 128 rows x 16 chunks of 16B
        int row = lin >> 4;
        int cc  = lin & 15;
        cp16(base + wOff + swz(row, cc), src + (size_t)row * rstride + cc * 8);
    }
}

__global__ void __launch_bounds__(NT, 2) mhffn_hmma(
    const float* __restrict__ x,  const float* __restrict__ b1,
    const float* __restrict__ b2, float* __restrict__ out)
{
    extern __shared__ char smem[];
    const uint32_t sb = smem_u32(smem);
    const int t    = threadIdx.x;
    const int lane = t & 31;
    const int wid  = t >> 5;
    const int wm   = wid >> 2;   // 0..1 (M direction, 32 rows each)
    const int wn   = wid & 3;    // 0..3 (N direction, 32 cols each)
    const int h    = blockIdx.y;
    const int m0   = blockIdx.x * MT;

    float* b1s = (float*)(smem + SM_B1S);
    float* b2s = (float*)(smem + SM_B2S);
    if (t < 128) b2s[t] = b2[h * HD + t];

    const __half* w1base = g_W1 + (size_t)h * FF * HD;   // [FF][HD]
    const __half* w2base = g_W2 + (size_t)h * HD * FF;   // [HD][FF]

    // ---- prefetch W1 chunk 0 into WA ----
    w_copy_async(sb, SM_WA, w1base, HD, t);
    CP_COMMIT();

    // ---- X tile load (fp32 -> fp16) ----
    #pragma unroll
    for (int i = 0; i < 8; ++i) {
        int lin = i * NT + t;               // 64 rows x 32 float4
        int row = lin >> 5;
        int k4  = (lin & 31) << 2;
        float4 v = *(const float4*)(x + (size_t)(m0 + row) * DM + h * HD + k4);
        uint32_t o = swz(row, k4 >> 3) + ((k4 & 4) << 1);
        *(uint2*)(smem + SM_X + o) = make_uint2(
            pack_h2(__float2half_rn(v.x), __float2half_rn(v.y)),
            pack_h2(__float2half_rn(v.z), __float2half_rn(v.w)));
    }

    float oacc[2][4][4];
    #pragma unroll
    for (int i = 0; i < 2; ++i)
        #pragma unroll
        for (int j = 0; j < 4; ++j)
            #pragma unroll
            for (int q = 0; q < 4; ++q) oacc[i][j][q] = 0.0f;

    #pragma unroll 1
    for (int c = 0; c < 4; ++c) {
        // ---- W1(c) arrived; X (c=0) / prev-chunk reads complete ----
        CP_WAIT(0);
        __syncthreads();
        if (t < 128) b1s[t] = b1[(size_t)h * FF + c * FC + t];

        // stream W2(c) into WB while gemm1 runs on WA
        w_copy_async(sb, SM_WB, w2base + c * FC, FF, t);
        CP_COMMIT();

        // ---- stage 1: H = relu(X @ W1c + b1c) ----
        float acc[2][4][4];
        #pragma unroll
        for (int i = 0; i < 2; ++i)
            #pragma unroll
            for (int j = 0; j < 4; ++j)
                #pragma unroll
                for (int q = 0; q < 4; ++q) acc[i][j][q] = 0.0f;
        gemm_tile(sb, SM_X, SM_WA, lane, wm, wn, acc);
        __syncthreads();   // WA reads done (safe to refill)

        // stream W1(c+1) into WA while epilogue runs (always commit: group math)
        if (c < 3) w_copy_async(sb, SM_WA, w1base + (size_t)(c + 1) * FC * HD, HD, t);
        CP_COMMIT();

        // H epilogue: +b1, relu -> fp16 H tile (A-layout [m][f])
        #pragma unroll
        for (int mt = 0; mt < 2; ++mt)
            #pragma unroll
            for (int nt = 0; nt < 4; ++nt) {
                int m = wm * 32 + mt * 16 + (lane >> 2);
                int f = wn * 32 + nt * 8 + 2 * (lane & 3);
                float v0 = fmaxf(acc[mt][nt][0] + b1s[f],     0.0f);
                float v1 = fmaxf(acc[mt][nt][1] + b1s[f + 1], 0.0f);
                float v2 = fmaxf(acc[mt][nt][2] + b1s[f],     0.0f);
                float v3 = fmaxf(acc[mt][nt][3] + b1s[f + 1], 0.0f);
                uint32_t o0 = swz(m,     f >> 3) + ((f & 7) << 1);
                uint32_t o1 = swz(m + 8, f >> 3) + ((f & 7) << 1);
                *(uint32_t*)(smem + SM_H + o0) =
                    pack_h2(__float2half_rn(v0), __float2half_rn(v1));
                *(uint32_t*)(smem + SM_H + o1) =
                    pack_h2(__float2half_rn(v2), __float2half_rn(v3));
            }

        // ---- W2(c) arrived (W1(c+1) may still be in flight); H visible ----
        CP_WAIT(1);
        __syncthreads();

        // ---- stage 2: OUT += H @ W2c ----
        gemm_tile(sb, SM_H, SM_WB, lane, wm, wn, oacc);
    }

    // ---- OUT epilogue: +b2, write fp32 ----
    #pragma unroll
    for (int mt = 0; mt < 2; ++mt)
        #pragma unroll
        for (int nt = 0; nt < 4; ++nt) {
            int m = wm * 32 + mt * 16 + (lane >> 2);
            int n = wn * 32 + nt * 8 + 2 * (lane & 3);
            float2 v0 = make_float2(oacc[mt][nt][0] + b2s[n],
                                    oacc[mt][nt][1] + b2s[n + 1]);
            float2 v1 = make_float2(oacc[mt][nt][2] + b2s[n],
                                    oacc[mt][nt][3] + b2s[n + 1]);
            *(float2*)(out + (size_t)(m0 + m)     * DM + h * HD + n) = v0;
            *(float2*)(out + (size_t)(m0 + m + 8) * DM + h * HD + n) = v1;
        }
}

extern "C" void kernel_launch(void* const* d_in, const int* in_sizes, int n_in,
                              void* d_out, int out_size) {
    const float* x  = (const float*)d_in[0];
    const float* W1 = (const float*)d_in[1];
    const float* b1 = (const float*)d_in[2];
    const float* W2 = (const float*)d_in[3];
    const float* b2 = (const float*)d_in[4];
    float* out = (float*)d_out;

    // weight transpose + fp16 convert (every launch; deterministic)
    prep_kernel<<<8192, 256>>>(W1, W2);

    int M = in_sizes[0] / DM;   // 16384 tokens
    cudaFuncSetAttribute(mhffn_hmma, cudaFuncAttributeMaxDynamicSharedMemorySize,
                         (int)SMEM_BYTES);
    dim3 grid(M / MT, 16);
    mhffn_hmma<<<grid, NT, SMEM_BYTES>>>(x, b1, b2, out);
}